// round 15
// baseline (speedup 1.0000x reference)
#include <cuda_runtime.h>
#include <cuda_bf16.h>
#include <cstdint>

#define THREADS 384       // 8 consumer warps + 4 producer warps
#define GRID 152          // persistent: one CTA per SM
#define BM 64             // edges per tile
#define HID 256
#define INCH 256
#define NQ 4              // K quarters of 64

// ---- dynamic smem layout (bytes) ----
#define AHI(p)    ((p) * 8192)        // A hi, 64 rows x 128B, double buffered
#define B_OFF     16384               // 256 rows x 512B (XOR-swizzled)
#define SB1_OFF   147456
#define SW2_OFF   148480
#define IDX_OFF   149504              // set p: src[64] @ p*512, dst[64] @ +256
#define SPART_OFF 150528              // 64 rows x 4 wn x f32 = 1 KB
#define SMEM_DYN  151552

__device__ __nv_bfloat16 g_W1T_hi[HID * INCH];   // K-major [n][k]

__global__ void prep_w1(const float* __restrict__ W1) {
    int k = blockIdx.x;
    int n = threadIdx.x;
    g_W1T_hi[n * INCH + k] = __float2bfloat16(W1[k * HID + n]);
}

static __device__ __forceinline__ void mma16816(float* d, const uint32_t* a,
                                                uint32_t b0, uint32_t b1) {
    asm volatile(
        "mma.sync.aligned.m16n8k16.row.col.f32.bf16.bf16.f32 "
        "{%0,%1,%2,%3},{%4,%5,%6,%7},{%8,%9},{%0,%1,%2,%3};"
        : "+f"(d[0]), "+f"(d[1]), "+f"(d[2]), "+f"(d[3])
        : "r"(a[0]), "r"(a[1]), "r"(a[2]), "r"(a[3]), "r"(b0), "r"(b1));
}

// producer: LDG z quarter qk (idx set), product, bf16 cvt, STS -> A buffer
static __device__ __forceinline__ void produce_q(char* sm, const float* __restrict__ z,
                                                 int set, int qk, int adst, int tid_p) {
    const int* ssrc = (const int*)(sm + IDX_OFF + set * 512);
    const int* sdst = ssrc + 64;
    const int rb   = tid_p >> 4;            // 0..7
    const int klel = (tid_p & 15) << 2;     // 0..60
    float4 za[8], zb[8];
    #pragma unroll
    for (int j = 0; j < 8; j++) {
        int r = rb + j * 8;
        za[j] = *(const float4*)(z + ssrc[r] + qk * 64 + klel);
        zb[j] = *(const float4*)(z + sdst[r] + qk * 64 + klel);
    }
    #pragma unroll
    for (int j = 0; j < 8; j++) {
        int r = rb + j * 8;
        __nv_bfloat162 h01 = __floats2bfloat162_rn(za[j].x * zb[j].x, za[j].y * zb[j].y);
        __nv_bfloat162 h23 = __floats2bfloat162_rn(za[j].z * zb[j].z, za[j].w * zb[j].w);
        uint2 hv;
        hv.x = *(uint32_t*)&h01; hv.y = *(uint32_t*)&h23;
        int off = r * 128 + ((klel * 2) ^ ((r & 7) << 4));
        *(uint2*)(sm + adst + off) = hv;
    }
}

__global__ void __launch_bounds__(THREADS, 1)
edge_decoder_ws(const float* __restrict__ z,
                const int* __restrict__ src,
                const int* __restrict__ dst,
                const float* __restrict__ b1,
                const float* __restrict__ W2,
                const float* __restrict__ b2,
                float* __restrict__ out,
                int E, int Nn, int NT)
{
    extern __shared__ __align__(16) char sm[];
    const int tid  = threadIdx.x;
    const int lane = tid & 31;
    const int wid  = tid >> 5;       // 0..11
    // consumer decomposition (warps 0-7): M32 x N64 tiles
    const int wm   = wid & 1;
    const int wn   = wid >> 1;       // 0..3 for consumers
    const int g    = lane >> 2;
    const int c4   = (lane & 3) << 2;
    const int sw   = g << 4;

    float* s_b1 = (float*)(sm + SB1_OFF);
    float* s_w2 = (float*)(sm + SW2_OFF);

    // ---------- prologue ----------
    // resident B (XOR-swizzled 512B rows): 8192 x 16B
    {
        const char* gH = (const char*)g_W1T_hi;
        #pragma unroll
        for (int j = 0; j < 22; j++) {
            int q = tid + j * THREADS;
            if (q < 8192) {
                int n = q >> 5;
                int c16 = (q & 31) << 4;
                *(uint4*)(sm + B_OFF + n * 512 + (c16 ^ ((n & 7) << 4))) =
                    *(const uint4*)(gH + n * 512 + c16);
            }
        }
    }
    // idx set0 <- tile i0 = blockIdx.x (producer threads)
    if (tid >= 256) {
        int tid_p = tid - 256;
        int row = tid_p & 63;
        long long e = (long long)blockIdx.x * BM + row;
        if (e >= E) e = E - 1;
        int v = (tid_p < 64) ? src[e] : dst[e];
        v = (v < 0) ? 0 : (v >= Nn ? Nn - 1 : v);
        ((int*)(sm + IDX_OFF + ((tid_p < 64) ? 0 : 256)))[row] = v * INCH;
    }
    if (tid < 256) {
        s_b1[tid] = b1[tid];
        s_w2[tid] = W2[tid];
    }
    const float bias2 = b2[0];
    __syncthreads();

    // producers: build A[0] <- tile0 q0
    if (tid >= 256)
        produce_q(sm, z, 0, 0, AHI(0), tid - 256);

    // ---------- pipelined persistent loop ----------
    int it = 0;
    for (int i = blockIdx.x; i < NT; i += GRID, it++) {
        float acc[2][8][4];
        if (wid < 8) {
            #pragma unroll
            for (int mt = 0; mt < 2; mt++)
                #pragma unroll
                for (int nt = 0; nt < 8; nt++)
                    #pragma unroll
                    for (int k = 0; k < 4; k++) acc[mt][nt][k] = 0.f;
        }

        #pragma unroll
        for (int h = 0; h < NQ; h++) {
            __syncthreads();   // A[h&1] produced; A[(h+1)&1] consumed/free

            if (wid < 8) {
                // ---- consumer: MMA quarter h from A[h&1] (pure LDS+HMMA) ----
                const int ahi = AHI(h & 1);
                #pragma unroll
                for (int ks = 0; ks < 4; ks++) {
                    const int kb = ks * 32;
                    const int o0 = (kb ^ sw) + c4;
                    const int o1 = ((kb + 16) ^ sw) + c4;
                    uint32_t ah[2][4];
                    #pragma unroll
                    for (int mt = 0; mt < 2; mt++) {
                        const int rbb = (wm * 32 + mt * 16 + g) * 128;
                        ah[mt][0] = *(const uint32_t*)(sm + ahi + rbb + o0);
                        ah[mt][1] = *(const uint32_t*)(sm + ahi + rbb + o0 + 1024);
                        ah[mt][2] = *(const uint32_t*)(sm + ahi + rbb + o1);
                        ah[mt][3] = *(const uint32_t*)(sm + ahi + rbb + o1 + 1024);
                    }
                    #pragma unroll
                    for (int nt = 0; nt < 8; nt++) {
                        const int nrow = (wn * 64 + nt * 8 + g) * 512 + c4;
                        const int kc = h * 128 + kb;
                        uint32_t b0 = *(const uint32_t*)(sm + B_OFF + nrow + (kc ^ sw));
                        uint32_t b1r = *(const uint32_t*)(sm + B_OFF + nrow + ((kc + 16) ^ sw));
                        mma16816(acc[0][nt], ah[0], b0, b1r);
                        mma16816(acc[1][nt], ah[1], b0, b1r);
                    }
                }
            } else {
                // ---- producer ----
                int tid_p = tid - 256;
                if (h == 0) {
                    // prefetch idx(it+1) -> set (it+1)&1
                    int row = tid_p & 63;
                    long long e = ((long long)i + GRID) * BM + row;
                    if (e >= E) e = E - 1;
                    int v = (tid_p < 64) ? src[e] : dst[e];
                    v = (v < 0) ? 0 : (v >= Nn ? Nn - 1 : v);
                    ((int*)(sm + IDX_OFF + ((it + 1) & 1) * 512 + ((tid_p < 64) ? 0 : 256)))[row] = v * INCH;
                }
                int qk  = (h + 1) & 3;
                int set = (h == 3) ? ((it + 1) & 1) : (it & 1);
                produce_q(sm, z, set, qk, AHI((h + 1) & 1), tid_p);
            }
        }

        // ---------- fused epilogue (tile i, consumer warps) ----------
        if (wid < 8) {
            float pr[2][2];
            #pragma unroll
            for (int mt = 0; mt < 2; mt++) {
                float p0 = 0.f, p1 = 0.f;
                #pragma unroll
                for (int nt = 0; nt < 8; nt++) {
                    int c0 = wn * 64 + nt * 8 + (lane & 3) * 2;
                    float w2a = s_w2[c0],     b1a = s_b1[c0];
                    float w2b = s_w2[c0 + 1], b1b = s_b1[c0 + 1];
                    p0 = fmaf(fmaxf(acc[mt][nt][0] + b1a, 0.f), w2a, p0);
                    p0 = fmaf(fmaxf(acc[mt][nt][1] + b1b, 0.f), w2b, p0);
                    p1 = fmaf(fmaxf(acc[mt][nt][2] + b1a, 0.f), w2a, p1);
                    p1 = fmaf(fmaxf(acc[mt][nt][3] + b1b, 0.f), w2b, p1);
                }
                p0 += __shfl_xor_sync(0xffffffffu, p0, 1);
                p0 += __shfl_xor_sync(0xffffffffu, p0, 2);
                p1 += __shfl_xor_sync(0xffffffffu, p1, 1);
                p1 += __shfl_xor_sync(0xffffffffu, p1, 2);
                pr[mt][0] = p0; pr[mt][1] = p1;
            }
            float* s_part = (float*)(sm + SPART_OFF);   // [64][4]
            if ((lane & 3) == 0) {
                #pragma unroll
                for (int mt = 0; mt < 2; mt++) {
                    int r = wm * 32 + mt * 16 + g;
                    s_part[r * 4 + wn]       = pr[mt][0];
                    s_part[(r + 8) * 4 + wn] = pr[mt][1];
                }
            }
        }
        __syncthreads();
        if (tid < BM) {
            float* s_part = (float*)(sm + SPART_OFF);
            float p = s_part[tid * 4 + 0] + s_part[tid * 4 + 1] +
                      s_part[tid * 4 + 2] + s_part[tid * 4 + 3];
            long long e = (long long)i * BM + tid;
            if (e < E)
                out[e] = 1.f / (1.f + __expf(-(p + bias2)));
        }
        // next tile h=0 top sync orders s_part reuse
    }
}

extern "C" void kernel_launch(void* const* d_in, const int* in_sizes, int n_in,
                              void* d_out, int out_size) {
    // size-based input mapping (dict order confirmed: z,src,dst,W1,b1,W2,b2)
    int idx_z = -1, idx_w1 = -1, idx_b2 = -1;
    int idx_e1 = -1, idx_e2 = -1, idx_s1 = -1, idx_s2 = -1;
    for (int i = 0; i < n_in; i++) {
        int s = in_sizes[i];
        if (s == 25600000)      idx_z = i;
        else if (s == 65536)    idx_w1 = i;
        else if (s == 1)        idx_b2 = i;
        else if (s == 1000000) { if (idx_e1 < 0) idx_e1 = i; else idx_e2 = i; }
        else if (s == 256)     { if (idx_s1 < 0) idx_s1 = i; else idx_s2 = i; }
    }
    int idx_b1 = (idx_z == 0) ? idx_s1 : idx_s2;
    int idx_w2 = (idx_z == 0) ? idx_s2 : idx_s1;

    const float* z   = (const float*)d_in[idx_z];
    const int*   src = (const int*)d_in[idx_e1];
    const int*   dst = (const int*)d_in[idx_e2];
    const float* W1  = (const float*)d_in[idx_w1];
    const float* b1  = (const float*)d_in[idx_b1];
    const float* W2  = (const float*)d_in[idx_w2];
    const float* b2  = (const float*)d_in[idx_b2];
    float* out = (float*)d_out;

    int E  = in_sizes[idx_e1];
    int Nn = in_sizes[idx_z] / INCH;
    int NT = (E + BM - 1) / BM;     // 15625

    prep_w1<<<INCH, HID>>>(W1);

    static int smem_set = 0;
    if (!smem_set) {
        cudaFuncSetAttribute(edge_decoder_ws,
                             cudaFuncAttributeMaxDynamicSharedMemorySize, SMEM_DYN);
        smem_set = 1;
    }
    edge_decoder_ws<<<GRID, THREADS, SMEM_DYN>>>(z, src, dst, b1, W2, b2,
                                                 out, E, Nn, NT);
}

// round 16
// speedup vs baseline: 1.0613x; 1.0613x over previous
#include <cuda_runtime.h>
#include <cuda_bf16.h>
#include <cstdint>

#define THREADS 256
#define GRID 152          // persistent: one CTA per SM
#define BM 64             // edges per tile
#define HID 256
#define INCH 256
#define NQ 4              // K quarters of 64

// ---- dynamic smem layout (bytes) ----
#define AHI(p)    ((p) * 8192)        // A hi, 64 rows x 128B, double buffered
#define B_OFF     16384               // 256 rows x 512B (XOR-swizzled)
#define SB1_OFF   147456
#define SW2_OFF   148480
#define IDX_OFF   149504              // set p: src[64] @ p*512, dst[64] @ +256
#define SPART_OFF 150528              // 64 x 4 floats
#define SMEM_DYN  151552

__device__ __nv_bfloat16 g_W1T_hi[HID * INCH];   // K-major [n][k]

__global__ void prep_w1(const float* __restrict__ W1) {
    int k = blockIdx.x;
    int n = threadIdx.x;
    g_W1T_hi[n * INCH + k] = __float2bfloat16(W1[k * HID + n]);
}

static __device__ __forceinline__ void mma16816(float* d, const uint32_t* a,
                                                uint32_t b0, uint32_t b1) {
    asm volatile(
        "mma.sync.aligned.m16n8k16.row.col.f32.bf16.bf16.f32 "
        "{%0,%1,%2,%3},{%4,%5,%6,%7},{%8,%9},{%0,%1,%2,%3};"
        : "+f"(d[0]), "+f"(d[1]), "+f"(d[2]), "+f"(d[3])
        : "r"(a[0]), "r"(a[1]), "r"(a[2]), "r"(a[3]), "r"(b0), "r"(b1));
}

static __device__ __forceinline__ void ldsm4(uint32_t* r, uint32_t addr) {
    asm volatile(
        "ldmatrix.sync.aligned.m8n8.x4.shared.b16 {%0,%1,%2,%3}, [%4];"
        : "=r"(r[0]), "=r"(r[1]), "=r"(r[2]), "=r"(r[3]) : "r"(addr));
}

static __device__ __forceinline__ uint32_t smem_u32(const void* p) {
    uint32_t a;
    asm("{ .reg .u64 t; cvta.to.shared.u64 t, %1; cvt.u32.u64 %0, t; }" : "=r"(a) : "l"(p));
    return a;
}

__global__ void __launch_bounds__(THREADS, 1)
edge_decoder_ldsm(const float* __restrict__ z,
                  const int* __restrict__ src,
                  const int* __restrict__ dst,
                  const float* __restrict__ b1,
                  const float* __restrict__ W2,
                  const float* __restrict__ b2,
                  float* __restrict__ out,
                  int E, int Nn, int NT)
{
    extern __shared__ __align__(16) char sm[];
    const int tid  = threadIdx.x;
    const int lane = tid & 31;
    const int wid  = tid >> 5;
    const int wm   = wid & 1;        // M half: rows wm*32..+32
    const int wn   = wid >> 1;       // N quarter: cols wn*64..+64
    const int g    = lane >> 2;
    const int rowbase = tid >> 4;    // convert row base 0..15
    const int klel    = (tid & 15) << 2;
    const uint32_t sb = smem_u32(sm);

    float* s_b1 = (float*)(sm + SB1_OFF);
    float* s_w2 = (float*)(sm + SW2_OFF);

    // ---- per-lane ldmatrix address constants ----
    const int j  = lane >> 3;        // matrix index 0..3
    const int jr = lane & 7;         // row within matrix
    // A: matrix j -> (m-subtile j&1, k16-half j>>1)
    int offA[2][4];                  // [mt][ks] byte offsets inside an A buffer
    #pragma unroll
    for (int mt = 0; mt < 2; mt++) {
        int rowA = wm * 32 + mt * 16 + (j & 1) * 8 + jr;
        int swA  = (rowA & 7) << 4;
        #pragma unroll
        for (int ks = 0; ks < 4; ks++)
            offA[mt][ks] = rowA * 128 + ((ks * 32 + (j >> 1) * 16) ^ swA);
    }
    // B: matrix j -> (nt-pair member j>>1, k16-half j&1)
    int rowB512[4], swB[4];
    const int kc16 = (j & 1) * 16;
    #pragma unroll
    for (int p = 0; p < 4; p++) {
        int rowB = wn * 64 + (2 * p + (j >> 1)) * 8 + jr;
        rowB512[p] = rowB * 512;
        swB[p] = (rowB & 7) << 4;
    }

    // ---------- prologue ----------
    {
        const char* gH = (const char*)g_W1T_hi;
        #pragma unroll
        for (int jj = 0; jj < 32; jj++) {
            int q = tid + jj * THREADS;
            int n = q >> 5;
            int c16 = (q & 31) << 4;
            *(uint4*)(sm + B_OFF + n * 512 + (c16 ^ ((n & 7) << 4))) =
                *(const uint4*)(gH + n * 512 + c16);
        }
    }
    if (tid < 128) {
        int row = tid & 63;
        long long e = (long long)blockIdx.x * BM + row;
        if (e >= E) e = E - 1;
        int v = (tid < 64) ? src[e] : dst[e];
        v = (v < 0) ? 0 : (v >= Nn ? Nn - 1 : v);
        ((int*)(sm + IDX_OFF + ((tid < 64) ? 0 : 256)))[row] = v * INCH;
    }
    s_b1[tid] = b1[tid];
    s_w2[tid] = W2[tid];
    const float bias2 = b2[0];
    __syncthreads();

    float4 zs[4], zd[4];
    // LDG q0 -> regs; convert -> A[0]; LDG q1 -> regs
    {
        const int* ssrc = (const int*)(sm + IDX_OFF);
        const int* sdst = ssrc + 64;
        #pragma unroll
        for (int jj = 0; jj < 4; jj++) {
            int m = rowbase + jj * 16;
            zs[jj] = *(const float4*)(z + ssrc[m] + klel);
            zd[jj] = *(const float4*)(z + sdst[m] + klel);
        }
        #pragma unroll
        for (int jj = 0; jj < 4; jj++) {
            int m = rowbase + jj * 16;
            __nv_bfloat162 h01 = __floats2bfloat162_rn(zs[jj].x * zd[jj].x, zs[jj].y * zd[jj].y);
            __nv_bfloat162 h23 = __floats2bfloat162_rn(zs[jj].z * zd[jj].z, zs[jj].w * zd[jj].w);
            uint2 hv;
            hv.x = *(uint32_t*)&h01; hv.y = *(uint32_t*)&h23;
            int off = m * 128 + ((klel * 2) ^ ((m & 7) << 4));
            *(uint2*)(sm + AHI(0) + off) = hv;
        }
        #pragma unroll
        for (int jj = 0; jj < 4; jj++) {
            int m = rowbase + jj * 16;
            zs[jj] = *(const float4*)(z + ssrc[m] + 64 + klel);
            zd[jj] = *(const float4*)(z + sdst[m] + 64 + klel);
        }
    }

    // ---------- pipelined persistent loop ----------
    int it = 0;
    for (int i = blockIdx.x; i < NT; i += GRID, it++) {
        float acc[2][8][4];
        #pragma unroll
        for (int mt = 0; mt < 2; mt++)
            #pragma unroll
            for (int nt = 0; nt < 8; nt++)
                #pragma unroll
                for (int k = 0; k < 4; k++) acc[mt][nt][k] = 0.f;

        #pragma unroll
        for (int h = 0; h < NQ; h++) {
            __syncthreads();   // A[h&1] visible; A[(h+1)&1] free

            if (h == 1 && tid < 128) {
                int row = tid & 63;
                long long e = ((long long)i + GRID) * BM + row;
                if (e >= E) e = E - 1;
                int v = (tid < 64) ? src[e] : dst[e];
                v = (v < 0) ? 0 : (v >= Nn ? Nn - 1 : v);
                ((int*)(sm + IDX_OFF + ((it + 1) & 1) * 512 + ((tid < 64) ? 0 : 256)))[row] = v * INCH;
            }

            // ---- MMA quarter h from A[h&1], ldmatrix fragments ----
            const uint32_t aBase = sb + AHI(h & 1);
            const uint32_t bBase = sb + B_OFF;
            const int hk = h * 128;
            #pragma unroll
            for (int ks = 0; ks < 4; ks++) {
                uint32_t a0[4], a1[4];
                ldsm4(a0, aBase + offA[0][ks]);
                ldsm4(a1, aBase + offA[1][ks]);
                uint32_t bb[4][4];
                #pragma unroll
                for (int p = 0; p < 4; p++)
                    ldsm4(bb[p], bBase + rowB512[p] + ((hk + ks * 32 + kc16) ^ swB[p]));
                #pragma unroll
                for (int p = 0; p < 4; p++) {
                    mma16816(acc[0][2 * p],     a0, bb[p][0], bb[p][1]);
                    mma16816(acc[1][2 * p],     a1, bb[p][0], bb[p][1]);
                    mma16816(acc[0][2 * p + 1], a0, bb[p][2], bb[p][3]);
                    mma16816(acc[1][2 * p + 1], a1, bb[p][2], bb[p][3]);
                }
            }

            // ---- convert staged regs (quarter h+1) -> A[(h+1)&1] ----
            {
                const int adst = AHI((h + 1) & 1);
                #pragma unroll
                for (int jj = 0; jj < 4; jj++) {
                    int m = rowbase + jj * 16;
                    __nv_bfloat162 h01 = __floats2bfloat162_rn(zs[jj].x * zd[jj].x, zs[jj].y * zd[jj].y);
                    __nv_bfloat162 h23 = __floats2bfloat162_rn(zs[jj].z * zd[jj].z, zs[jj].w * zd[jj].w);
                    uint2 hv;
                    hv.x = *(uint32_t*)&h01; hv.y = *(uint32_t*)&h23;
                    int off = m * 128 + ((klel * 2) ^ ((m & 7) << 4));
                    *(uint2*)(sm + adst + off) = hv;
                }
            }

            // ---- issue LDG for quarter h+2 ----
            {
                int qk  = (h + 2) & 3;
                int set = (h >= 2) ? ((it + 1) & 1) : (it & 1);
                const int* ssrc = (const int*)(sm + IDX_OFF + set * 512);
                const int* sdst = ssrc + 64;
                #pragma unroll
                for (int jj = 0; jj < 4; jj++) {
                    int m = rowbase + jj * 16;
                    zs[jj] = *(const float4*)(z + ssrc[m] + qk * 64 + klel);
                    zd[jj] = *(const float4*)(z + sdst[m] + qk * 64 + klel);
                }
            }
        }

        // ---------- fused epilogue (tile i) ----------
        float pr[2][2];
        #pragma unroll
        for (int mt = 0; mt < 2; mt++) {
            float p0 = 0.f, p1 = 0.f;
            #pragma unroll
            for (int nt = 0; nt < 8; nt++) {
                int c0 = wn * 64 + nt * 8 + (lane & 3) * 2;
                float w2a = s_w2[c0],     b1a = s_b1[c0];
                float w2b = s_w2[c0 + 1], b1b = s_b1[c0 + 1];
                p0 = fmaf(fmaxf(acc[mt][nt][0] + b1a, 0.f), w2a, p0);
                p0 = fmaf(fmaxf(acc[mt][nt][1] + b1b, 0.f), w2b, p0);
                p1 = fmaf(fmaxf(acc[mt][nt][2] + b1a, 0.f), w2a, p1);
                p1 = fmaf(fmaxf(acc[mt][nt][3] + b1b, 0.f), w2b, p1);
            }
            p0 += __shfl_xor_sync(0xffffffffu, p0, 1);
            p0 += __shfl_xor_sync(0xffffffffu, p0, 2);
            p1 += __shfl_xor_sync(0xffffffffu, p1, 1);
            p1 += __shfl_xor_sync(0xffffffffu, p1, 2);
            pr[mt][0] = p0; pr[mt][1] = p1;
        }

        float* s_part = (float*)(sm + SPART_OFF);
        if ((lane & 3) == 0) {
            #pragma unroll
            for (int mt = 0; mt < 2; mt++) {
                int r = wm * 32 + mt * 16 + g;
                s_part[r * 4 + wn]       = pr[mt][0];
                s_part[(r + 8) * 4 + wn] = pr[mt][1];
            }
        }
        __syncthreads();
        if (tid < BM) {
            float p = s_part[tid * 4 + 0] + s_part[tid * 4 + 1] +
                      s_part[tid * 4 + 2] + s_part[tid * 4 + 3];
            long long e = (long long)i * BM + tid;
            if (e < E)
                out[e] = 1.f / (1.f + __expf(-(p + bias2)));
        }
    }
}

extern "C" void kernel_launch(void* const* d_in, const int* in_sizes, int n_in,
                              void* d_out, int out_size) {
    // size-based input mapping (dict order confirmed: z,src,dst,W1,b1,W2,b2)
    int idx_z = -1, idx_w1 = -1, idx_b2 = -1;
    int idx_e1 = -1, idx_e2 = -1, idx_s1 = -1, idx_s2 = -1;
    for (int i = 0; i < n_in; i++) {
        int s = in_sizes[i];
        if (s == 25600000)      idx_z = i;
        else if (s == 65536)    idx_w1 = i;
        else if (s == 1)        idx_b2 = i;
        else if (s == 1000000) { if (idx_e1 < 0) idx_e1 = i; else idx_e2 = i; }
        else if (s == 256)     { if (idx_s1 < 0) idx_s1 = i; else idx_s2 = i; }
    }
    int idx_b1 = (idx_z == 0) ? idx_s1 : idx_s2;
    int idx_w2 = (idx_z == 0) ? idx_s2 : idx_s1;

    const float* z   = (const float*)d_in[idx_z];
    const int*   src = (const int*)d_in[idx_e1];
    const int*   dst = (const int*)d_in[idx_e2];
    const float* W1  = (const float*)d_in[idx_w1];
    const float* b1  = (const float*)d_in[idx_b1];
    const float* W2  = (const float*)d_in[idx_w2];
    const float* b2  = (const float*)d_in[idx_b2];
    float* out = (float*)d_out;

    int E  = in_sizes[idx_e1];
    int Nn = in_sizes[idx_z] / INCH;
    int NT = (E + BM - 1) / BM;     // 15625

    prep_w1<<<INCH, HID>>>(W1);

    static int smem_set = 0;
    if (!smem_set) {
        cudaFuncSetAttribute(edge_decoder_ldsm,
                             cudaFuncAttributeMaxDynamicSharedMemorySize, SMEM_DYN);
        smem_set = 1;
    }
    edge_decoder_ldsm<<<GRID, THREADS, SMEM_DYN>>>(z, src, dst, b1, W2, b2,
                                                   out, E, Nn, NT);
}

// round 17
// speedup vs baseline: 1.1159x; 1.0514x over previous
#include <cuda_runtime.h>
#include <cuda_bf16.h>
#include <cstdint>

#define THREADS 512
#define GRID 152          // persistent: one CTA per SM
#define BM 128            // edges per tile
#define HID 256
#define INCH 256
#define NQ 4              // K quarters of 64

// ---- dynamic smem layout (bytes) ----
#define AHI(p)    ((p) * 16384)       // A hi, 128 rows x 128B, double buffered
#define B_OFF     32768               // 256 rows x 512B (XOR-swizzled) = 128 KB
#define SB1_OFF   163840
#define SW2_OFF   164864
#define IDX_OFF   165888              // set p @ p*1024: src[128] @0, dst[128] @512
#define SPART_OFF 167936              // 128 rows x 8 wn x f32 = 4 KB
#define SMEM_DYN  172032

__device__ __nv_bfloat16 g_W1T_hi[HID * INCH];   // K-major [n][k]

__global__ void prep_w1(const float* __restrict__ W1) {
    int k = blockIdx.x;
    int n = threadIdx.x;
    g_W1T_hi[n * INCH + k] = __float2bfloat16(W1[k * HID + n]);
}

static __device__ __forceinline__ void mma16816(float* d, const uint32_t* a,
                                                uint32_t b0, uint32_t b1) {
    asm volatile(
        "mma.sync.aligned.m16n8k16.row.col.f32.bf16.bf16.f32 "
        "{%0,%1,%2,%3},{%4,%5,%6,%7},{%8,%9},{%0,%1,%2,%3};"
        : "+f"(d[0]), "+f"(d[1]), "+f"(d[2]), "+f"(d[3])
        : "r"(a[0]), "r"(a[1]), "r"(a[2]), "r"(a[3]), "r"(b0), "r"(b1));
}

static __device__ __forceinline__ void ldsm4(uint32_t* r, uint32_t addr) {
    asm volatile(
        "ldmatrix.sync.aligned.m8n8.x4.shared.b16 {%0,%1,%2,%3}, [%4];"
        : "=r"(r[0]), "=r"(r[1]), "=r"(r[2]), "=r"(r[3]) : "r"(addr));
}

static __device__ __forceinline__ uint32_t smem_u32(const void* p) {
    uint32_t a;
    asm("{ .reg .u64 t; cvta.to.shared.u64 t, %1; cvt.u32.u64 %0, t; }" : "=r"(a) : "l"(p));
    return a;
}

__global__ void __launch_bounds__(THREADS, 1)
edge_decoder_big(const float* __restrict__ z,
                 const int* __restrict__ src,
                 const int* __restrict__ dst,
                 const float* __restrict__ b1,
                 const float* __restrict__ W2,
                 const float* __restrict__ b2,
                 float* __restrict__ out,
                 int E, int Nn, int NT)
{
    extern __shared__ __align__(16) char sm[];
    const int tid  = threadIdx.x;
    const int lane = tid & 31;
    const int wid  = tid >> 5;       // 0..15
    const int wm   = wid & 1;        // M half: rows wm*64..+64
    const int wn   = wid >> 1;       // N eighth: cols wn*32..+32
    const int g    = lane >> 2;
    const int rowbase = tid >> 4;    // convert row base 0..31
    const int klel    = (tid & 15) << 2;
    const uint32_t sb = smem_u32(sm);

    float* s_b1 = (float*)(sm + SB1_OFF);
    float* s_w2 = (float*)(sm + SW2_OFF);

    // ---- per-lane ldmatrix address constants ----
    const int j  = lane >> 3;        // matrix index 0..3
    const int jr = lane & 7;
    // A: matrix j -> (m-subtile j&1, k16-half j>>1); 4 m-tiles of 16 rows
    int offA[4][4];                  // [mt][ks]
    #pragma unroll
    for (int mt = 0; mt < 4; mt++) {
        int rowA = wm * 64 + mt * 16 + (j & 1) * 8 + jr;
        int swA  = (rowA & 7) << 4;
        #pragma unroll
        for (int ks = 0; ks < 4; ks++)
            offA[mt][ks] = rowA * 128 + ((ks * 32 + (j >> 1) * 16) ^ swA);
    }
    // B: matrix j -> (nt-pair member j>>1, k16-half j&1); 2 nt-pairs cover N32
    int rowB512[2], swB[2];
    const int kc16 = (j & 1) * 16;
    #pragma unroll
    for (int p = 0; p < 2; p++) {
        int rowB = wn * 32 + (2 * p + (j >> 1)) * 8 + jr;
        rowB512[p] = rowB * 512;
        swB[p] = (rowB & 7) << 4;
    }

    // ---------- prologue ----------
    {
        const char* gH = (const char*)g_W1T_hi;
        #pragma unroll
        for (int jj = 0; jj < 16; jj++) {
            int q = tid + jj * THREADS;
            int n = q >> 5;
            int c16 = (q & 31) << 4;
            *(uint4*)(sm + B_OFF + n * 512 + (c16 ^ ((n & 7) << 4))) =
                *(const uint4*)(gH + n * 512 + c16);
        }
    }
    if (tid < 256) {
        int row = tid & 127;
        long long e = (long long)blockIdx.x * BM + row;
        if (e >= E) e = E - 1;
        int v = (tid < 128) ? src[e] : dst[e];
        v = (v < 0) ? 0 : (v >= Nn ? Nn - 1 : v);
        ((int*)(sm + IDX_OFF + ((tid < 128) ? 0 : 512)))[row] = v * INCH;
    }
    if (tid < 256) {
        s_b1[tid] = b1[tid];
        s_w2[tid] = W2[tid];
    }
    const float bias2 = b2[0];
    __syncthreads();

    float4 zs[4], zd[4];
    // LDG q0 -> regs; convert -> A[0]; LDG q1 -> regs
    {
        const int* ssrc = (const int*)(sm + IDX_OFF);
        const int* sdst = (const int*)(sm + IDX_OFF + 512);
        #pragma unroll
        for (int jj = 0; jj < 4; jj++) {
            int m = rowbase + jj * 32;
            zs[jj] = *(const float4*)(z + ssrc[m] + klel);
            zd[jj] = *(const float4*)(z + sdst[m] + klel);
        }
        #pragma unroll
        for (int jj = 0; jj < 4; jj++) {
            int m = rowbase + jj * 32;
            __nv_bfloat162 h01 = __floats2bfloat162_rn(zs[jj].x * zd[jj].x, zs[jj].y * zd[jj].y);
            __nv_bfloat162 h23 = __floats2bfloat162_rn(zs[jj].z * zd[jj].z, zs[jj].w * zd[jj].w);
            uint2 hv;
            hv.x = *(uint32_t*)&h01; hv.y = *(uint32_t*)&h23;
            int off = m * 128 + ((klel * 2) ^ ((m & 7) << 4));
            *(uint2*)(sm + AHI(0) + off) = hv;
        }
        #pragma unroll
        for (int jj = 0; jj < 4; jj++) {
            int m = rowbase + jj * 32;
            zs[jj] = *(const float4*)(z + ssrc[m] + 64 + klel);
            zd[jj] = *(const float4*)(z + sdst[m] + 64 + klel);
        }
    }

    // ---------- pipelined persistent loop ----------
    int it = 0;
    for (int i = blockIdx.x; i < NT; i += GRID, it++) {
        float acc[4][4][4];
        #pragma unroll
        for (int mt = 0; mt < 4; mt++)
            #pragma unroll
            for (int nt = 0; nt < 4; nt++)
                #pragma unroll
                for (int k = 0; k < 4; k++) acc[mt][nt][k] = 0.f;

        #pragma unroll
        for (int h = 0; h < NQ; h++) {
            __syncthreads();   // A[h&1] visible; A[(h+1)&1] free

            if (h == 1 && tid < 256) {
                int row = tid & 127;
                long long e = ((long long)i + GRID) * BM + row;
                if (e >= E) e = E - 1;
                int v = (tid < 128) ? src[e] : dst[e];
                v = (v < 0) ? 0 : (v >= Nn ? Nn - 1 : v);
                ((int*)(sm + IDX_OFF + ((it + 1) & 1) * 1024 + ((tid < 128) ? 0 : 512)))[row] = v * INCH;
            }

            // ---- MMA quarter h from A[h&1] (ldmatrix fragments) ----
            const uint32_t aBase = sb + AHI(h & 1);
            const uint32_t bBase = sb + B_OFF;
            const int hk = h * 128;
            #pragma unroll
            for (int ks = 0; ks < 4; ks++) {
                uint32_t a[4][4];
                #pragma unroll
                for (int mt = 0; mt < 4; mt++)
                    ldsm4(a[mt], aBase + offA[mt][ks]);
                uint32_t bb[2][4];
                #pragma unroll
                for (int p = 0; p < 2; p++)
                    ldsm4(bb[p], bBase + rowB512[p] + ((hk + ks * 32 + kc16) ^ swB[p]));
                #pragma unroll
                for (int p = 0; p < 2; p++)
                    #pragma unroll
                    for (int mt = 0; mt < 4; mt++) {
                        mma16816(acc[mt][2 * p],     a[mt], bb[p][0], bb[p][1]);
                        mma16816(acc[mt][2 * p + 1], a[mt], bb[p][2], bb[p][3]);
                    }
            }

            // ---- convert staged regs (quarter h+1) -> A[(h+1)&1] ----
            {
                const int adst = AHI((h + 1) & 1);
                #pragma unroll
                for (int jj = 0; jj < 4; jj++) {
                    int m = rowbase + jj * 32;
                    __nv_bfloat162 h01 = __floats2bfloat162_rn(zs[jj].x * zd[jj].x, zs[jj].y * zd[jj].y);
                    __nv_bfloat162 h23 = __floats2bfloat162_rn(zs[jj].z * zd[jj].z, zs[jj].w * zd[jj].w);
                    uint2 hv;
                    hv.x = *(uint32_t*)&h01; hv.y = *(uint32_t*)&h23;
                    int off = m * 128 + ((klel * 2) ^ ((m & 7) << 4));
                    *(uint2*)(sm + adst + off) = hv;
                }
            }

            // ---- issue LDG for quarter h+2 ----
            {
                int qk  = (h + 2) & 3;
                int set = (h >= 2) ? ((it + 1) & 1) : (it & 1);
                const int* ssrc = (const int*)(sm + IDX_OFF + set * 1024);
                const int* sdst = (const int*)(sm + IDX_OFF + set * 1024 + 512);
                #pragma unroll
                for (int jj = 0; jj < 4; jj++) {
                    int m = rowbase + jj * 32;
                    zs[jj] = *(const float4*)(z + ssrc[m] + qk * 64 + klel);
                    zd[jj] = *(const float4*)(z + sdst[m] + qk * 64 + klel);
                }
            }
        }

        // ---------- fused epilogue (tile i) ----------
        float* s_part = (float*)(sm + SPART_OFF);   // [128][8]
        #pragma unroll
        for (int mt = 0; mt < 4; mt++) {
            float p0 = 0.f, p1 = 0.f;
            #pragma unroll
            for (int nt = 0; nt < 4; nt++) {
                int c0 = wn * 32 + nt * 8 + (lane & 3) * 2;
                float w2a = s_w2[c0],     b1a = s_b1[c0];
                float w2b = s_w2[c0 + 1], b1b = s_b1[c0 + 1];
                p0 = fmaf(fmaxf(acc[mt][nt][0] + b1a, 0.f), w2a, p0);
                p0 = fmaf(fmaxf(acc[mt][nt][1] + b1b, 0.f), w2b, p0);
                p1 = fmaf(fmaxf(acc[mt][nt][2] + b1a, 0.f), w2a, p1);
                p1 = fmaf(fmaxf(acc[mt][nt][3] + b1b, 0.f), w2b, p1);
            }
            p0 += __shfl_xor_sync(0xffffffffu, p0, 1);
            p0 += __shfl_xor_sync(0xffffffffu, p0, 2);
            p1 += __shfl_xor_sync(0xffffffffu, p1, 1);
            p1 += __shfl_xor_sync(0xffffffffu, p1, 2);
            if ((lane & 3) == 0) {
                int r = wm * 64 + mt * 16 + g;
                s_part[r * 8 + wn]       = p0;
                s_part[(r + 8) * 8 + wn] = p1;
            }
        }
        __syncthreads();
        if (tid < BM) {
            float p = 0.f;
            #pragma unroll
            for (int k = 0; k < 8; k++) p += s_part[tid * 8 + k];
            long long e = (long long)i * BM + tid;
            if (e < E)
                out[e] = 1.f / (1.f + __expf(-(p + bias2)));
        }
        // next tile h=0 top sync orders s_part reuse
    }
}

extern "C" void kernel_launch(void* const* d_in, const int* in_sizes, int n_in,
                              void* d_out, int out_size) {
    // size-based input mapping (dict order confirmed: z,src,dst,W1,b1,W2,b2)
    int idx_z = -1, idx_w1 = -1, idx_b2 = -1;
    int idx_e1 = -1, idx_e2 = -1, idx_s1 = -1, idx_s2 = -1;
    for (int i = 0; i < n_in; i++) {
        int s = in_sizes[i];
        if (s == 25600000)      idx_z = i;
        else if (s == 65536)    idx_w1 = i;
        else if (s == 1)        idx_b2 = i;
        else if (s == 1000000) { if (idx_e1 < 0) idx_e1 = i; else idx_e2 = i; }
        else if (s == 256)     { if (idx_s1 < 0) idx_s1 = i; else idx_s2 = i; }
    }
    int idx_b1 = (idx_z == 0) ? idx_s1 : idx_s2;
    int idx_w2 = (idx_z == 0) ? idx_s2 : idx_s1;

    const float* z   = (const float*)d_in[idx_z];
    const int*   src = (const int*)d_in[idx_e1];
    const int*   dst = (const int*)d_in[idx_e2];
    const float* W1  = (const float*)d_in[idx_w1];
    const float* b1  = (const float*)d_in[idx_b1];
    const float* W2  = (const float*)d_in[idx_w2];
    const float* b2  = (const float*)d_in[idx_b2];
    float* out = (float*)d_out;

    int E  = in_sizes[idx_e1];
    int Nn = in_sizes[idx_z] / INCH;
    int NT = (E + BM - 1) / BM;     // 7813

    prep_w1<<<INCH, HID>>>(W1);

    static int smem_set = 0;
    if (!smem_set) {
        cudaFuncSetAttribute(edge_decoder_big,
                             cudaFuncAttributeMaxDynamicSharedMemorySize, SMEM_DYN);
        smem_set = 1;
    }
    edge_decoder_big<<<GRID, THREADS, SMEM_DYN>>>(z, src, dst, b1, W2, b2,
                                                  out, E, Nn, NT);
}